// round 6
// baseline (speedup 1.0000x reference)
#include <cuda_runtime.h>
#include <float.h>

// Per-channel min/max over [C, N] fp32 (C=1024, N=32768).
// One CTA per channel (single wave). Single contiguous stream per CTA,
// guard-free exact trip count, dual accumulators for reduce-chain ILP,
// occ-6 register budget for deeper load batching.

__global__ void __launch_bounds__(256, 6)
minmax_r6_kernel(const float4* __restrict__ in, float* __restrict__ out,
                 int C, int N4) {
    const int c = blockIdx.x;
    const float4* __restrict__ p = in + (size_t)c * N4 + threadIdx.x;

    const int iters = N4 >> 8;          // N4 / 256, exact (32 for N=32768)

    float mn0 = FLT_MAX,  mn1 = FLT_MAX;
    float mx0 = -FLT_MAX, mx1 = -FLT_MAX;

    int k = 0;
    // Main unrolled loop: 8 independent LDG.128 per iteration window,
    // accumulators alternate to halve the serial FMNMX chain.
    for (; k + 8 <= iters; k += 8) {
        #pragma unroll
        for (int u = 0; u < 8; u += 2) {
            float4 a = p[(size_t)(k + u) * 256];
            float4 b = p[(size_t)(k + u + 1) * 256];
            mn0 = fminf(mn0, fminf(fminf(a.x, a.y), fminf(a.z, a.w)));
            mx0 = fmaxf(mx0, fmaxf(fmaxf(a.x, a.y), fmaxf(a.z, a.w)));
            mn1 = fminf(mn1, fminf(fminf(b.x, b.y), fminf(b.z, b.w)));
            mx1 = fmaxf(mx1, fmaxf(fmaxf(b.x, b.y), fmaxf(b.z, b.w)));
        }
    }
    // Tail (only for shapes where iters % 8 != 0)
    for (; k < iters; ++k) {
        float4 a = p[(size_t)k * 256];
        mn0 = fminf(mn0, fminf(fminf(a.x, a.y), fminf(a.z, a.w)));
        mx0 = fmaxf(mx0, fmaxf(fmaxf(a.x, a.y), fmaxf(a.z, a.w)));
    }

    float mn = fminf(mn0, mn1);
    float mx = fmaxf(mx0, mx1);

    // Warp butterfly reduction
    #pragma unroll
    for (int o = 16; o > 0; o >>= 1) {
        mn = fminf(mn, __shfl_xor_sync(0xffffffffu, mn, o));
        mx = fmaxf(mx, __shfl_xor_sync(0xffffffffu, mx, o));
    }

    __shared__ float smn[8], smx[8];
    const int wid = threadIdx.x >> 5;
    const int lid = threadIdx.x & 31;
    if (lid == 0) { smn[wid] = mn; smx[wid] = mx; }
    __syncthreads();

    if (threadIdx.x == 0) {
        #pragma unroll
        for (int w = 1; w < 8; ++w) {
            mn = fminf(mn, smn[w]);
            mx = fmaxf(mx, smx[w]);
        }
        out[c]     = mn;   // min_vals
        out[C + c] = mx;   // max_vals
    }
}

// Fallback: one CTA per channel, scalar-safe (any N).
__global__ void __launch_bounds__(256)
minmax_simple_kernel(const float* __restrict__ in, float* __restrict__ out,
                     int C, int N) {
    const int c = blockIdx.x;
    const float* row = in + (size_t)c * N;
    float mn = FLT_MAX, mx = -FLT_MAX;
    for (int i = threadIdx.x; i < N; i += 256) {
        float v = row[i];
        mn = fminf(mn, v);
        mx = fmaxf(mx, v);
    }
    #pragma unroll
    for (int o = 16; o > 0; o >>= 1) {
        mn = fminf(mn, __shfl_xor_sync(0xffffffffu, mn, o));
        mx = fmaxf(mx, __shfl_xor_sync(0xffffffffu, mx, o));
    }
    __shared__ float smn[8], smx[8];
    const int wid = threadIdx.x >> 5, lid = threadIdx.x & 31;
    if (lid == 0) { smn[wid] = mn; smx[wid] = mx; }
    __syncthreads();
    if (threadIdx.x == 0) {
        #pragma unroll
        for (int w = 1; w < 8; ++w) {
            mn = fminf(mn, smn[w]);
            mx = fmaxf(mx, smx[w]);
        }
        out[c] = mn;
        out[C + c] = mx;
    }
}

extern "C" void kernel_launch(void* const* d_in, const int* in_sizes, int n_in,
                              void* d_out, int out_size) {
    const float* in = (const float*)d_in[0];
    float* out = (float*)d_out;

    const int C = out_size / 2;       // 1024
    const int N = in_sizes[0] / C;    // 32768

    // Fast path: N divisible by 4 (float4) and N/4 divisible by 256
    // (guard-free 256-stride loop).
    if ((N & 3) == 0 && ((N >> 2) & 255) == 0) {
        minmax_r6_kernel<<<C, 256>>>((const float4*)in, out, C, N >> 2);
    } else {
        minmax_simple_kernel<<<C, 256>>>(in, out, C, N);
    }
}

// round 7
// speedup vs baseline: 1.0012x; 1.0012x over previous
#include <cuda_runtime.h>
#include <float.h>

// Per-channel min/max over [C, N] fp32 (C=1024, N=32768).
// One CTA per channel. Explicit batch-8 register-array loads force ptxas to
// front-batch 8 LDG.128 per warp (MLP=8): 48 warps/SM * 8 = 384 outstanding
// LDG.128 per SM, above the ~300 needed to cover DRAM latency at full BW.

__global__ void __launch_bounds__(256, 6)
minmax_r7_kernel(const float4* __restrict__ in, float* __restrict__ out,
                 int C, int N4) {
    const int c = blockIdx.x;
    const float4* __restrict__ p = in + (size_t)c * N4 + threadIdx.x;

    const int outer = N4 >> 11;         // N4 / (256*8) = 4 for N4=8192 (exact)

    float mn0 = FLT_MAX,  mn1 = FLT_MAX;
    float mx0 = -FLT_MAX, mx1 = -FLT_MAX;

    for (int k = 0; k < outer; ++k) {
        // Phase 1: 8 independent back-to-back LDG.128 (no consumers between).
        float4 v[8];
        #pragma unroll
        for (int u = 0; u < 8; ++u)
            v[u] = p[((size_t)k * 8 + u) * 256];

        // Phase 2: reduce; two accumulator pairs to cut the serial chain.
        #pragma unroll
        for (int u = 0; u < 8; u += 2) {
            mn0 = fminf(mn0, fminf(fminf(v[u].x, v[u].y), fminf(v[u].z, v[u].w)));
            mx0 = fmaxf(mx0, fmaxf(fmaxf(v[u].x, v[u].y), fmaxf(v[u].z, v[u].w)));
            mn1 = fminf(mn1, fminf(fminf(v[u+1].x, v[u+1].y), fminf(v[u+1].z, v[u+1].w)));
            mx1 = fmaxf(mx1, fmaxf(fmaxf(v[u+1].x, v[u+1].y), fmaxf(v[u+1].z, v[u+1].w)));
        }
    }

    float mn = fminf(mn0, mn1);
    float mx = fmaxf(mx0, mx1);

    // Warp butterfly reduction
    #pragma unroll
    for (int o = 16; o > 0; o >>= 1) {
        mn = fminf(mn, __shfl_xor_sync(0xffffffffu, mn, o));
        mx = fmaxf(mx, __shfl_xor_sync(0xffffffffu, mx, o));
    }

    __shared__ float smn[8], smx[8];
    const int wid = threadIdx.x >> 5;
    const int lid = threadIdx.x & 31;
    if (lid == 0) { smn[wid] = mn; smx[wid] = mx; }
    __syncthreads();

    if (threadIdx.x == 0) {
        #pragma unroll
        for (int w = 1; w < 8; ++w) {
            mn = fminf(mn, smn[w]);
            mx = fmaxf(mx, smx[w]);
        }
        out[c]     = mn;   // min_vals
        out[C + c] = mx;   // max_vals
    }
}

// Fallback: one CTA per channel, scalar-safe (any N).
__global__ void __launch_bounds__(256)
minmax_simple_kernel(const float* __restrict__ in, float* __restrict__ out,
                     int C, int N) {
    const int c = blockIdx.x;
    const float* row = in + (size_t)c * N;
    float mn = FLT_MAX, mx = -FLT_MAX;
    for (int i = threadIdx.x; i < N; i += 256) {
        float v = row[i];
        mn = fminf(mn, v);
        mx = fmaxf(mx, v);
    }
    #pragma unroll
    for (int o = 16; o > 0; o >>= 1) {
        mn = fminf(mn, __shfl_xor_sync(0xffffffffu, mn, o));
        mx = fmaxf(mx, __shfl_xor_sync(0xffffffffu, mx, o));
    }
    __shared__ float smn[8], smx[8];
    const int wid = threadIdx.x >> 5, lid = threadIdx.x & 31;
    if (lid == 0) { smn[wid] = mn; smx[wid] = mx; }
    __syncthreads();
    if (threadIdx.x == 0) {
        #pragma unroll
        for (int w = 1; w < 8; ++w) {
            mn = fminf(mn, smn[w]);
            mx = fmaxf(mx, smx[w]);
        }
        out[c] = mn;
        out[C + c] = mx;
    }
}

extern "C" void kernel_launch(void* const* d_in, const int* in_sizes, int n_in,
                              void* d_out, int out_size) {
    const float* in = (const float*)d_in[0];
    float* out = (float*)d_out;

    const int C = out_size / 2;       // 1024
    const int N = in_sizes[0] / C;    // 32768

    // Fast path: N/4 divisible by 2048 (guard-free batch-8 * 256-thread loop).
    if ((N & 3) == 0 && ((N >> 2) & 2047) == 0) {
        minmax_r7_kernel<<<C, 256>>>((const float4*)in, out, C, N >> 2);
    } else {
        minmax_simple_kernel<<<C, 256>>>(in, out, C, N);
    }
}

// round 9
// speedup vs baseline: 1.0674x; 1.0662x over previous
#include <cuda_runtime.h>
#include <float.h>

// Per-channel min/max over [C, N] fp32 (C=1024, N=32768).
// One CTA per channel, 512 threads (16 warps). Occupancy cap = 4 CTAs/SM
// = 64 warps = 100% theoretical: warp count (not per-warp MLP) is what
// hides DRAM latency on this part (evidence: DRAM% tracks achieved occ
// across R1/R6/R7). Guard-free 16-iteration streaming loop, R1's
// empirically-best interleaved load+reduce pattern.

__global__ void __launch_bounds__(512, 4)
minmax_r8_kernel(const float4* __restrict__ in, float* __restrict__ out,
                 int C, int N4) {
    const int c = blockIdx.x;
    const float4* __restrict__ p = in + (size_t)c * N4 + threadIdx.x;

    const int iters = N4 >> 9;          // N4 / 512, exact (16 for N=32768)

    float mn = FLT_MAX;
    float mx = -FLT_MAX;

    #pragma unroll 8
    for (int k = 0; k < iters; ++k) {
        float4 v = p[(size_t)k * 512];
        mn = fminf(mn, fminf(fminf(v.x, v.y), fminf(v.z, v.w)));
        mx = fmaxf(mx, fmaxf(fmaxf(v.x, v.y), fmaxf(v.z, v.w)));
    }

    // Warp butterfly reduction
    #pragma unroll
    for (int o = 16; o > 0; o >>= 1) {
        mn = fminf(mn, __shfl_xor_sync(0xffffffffu, mn, o));
        mx = fmaxf(mx, __shfl_xor_sync(0xffffffffu, mx, o));
    }

    __shared__ float smn[16], smx[16];
    const int wid = threadIdx.x >> 5;
    const int lid = threadIdx.x & 31;
    if (lid == 0) { smn[wid] = mn; smx[wid] = mx; }
    __syncthreads();

    // Final reduce across 16 warp partials by warp 0.
    if (wid == 0) {
        mn = (lid < 16) ? smn[lid] : FLT_MAX;
        mx = (lid < 16) ? smx[lid] : -FLT_MAX;
        #pragma unroll
        for (int o = 8; o > 0; o >>= 1) {
            mn = fminf(mn, __shfl_xor_sync(0xffffffffu, mn, o));
            mx = fmaxf(mx, __shfl_xor_sync(0xffffffffu, mx, o));
        }
        if (lid == 0) {
            out[c]     = mn;   // min_vals
            out[C + c] = mx;   // max_vals
        }
    }
}

// Fallback: one CTA per channel, scalar-safe (any N).
__global__ void __launch_bounds__(256)
minmax_simple_kernel(const float* __restrict__ in, float* __restrict__ out,
                     int C, int N) {
    const int c = blockIdx.x;
    const float* row = in + (size_t)c * N;
    float mn = FLT_MAX, mx = -FLT_MAX;
    for (int i = threadIdx.x; i < N; i += 256) {
        float v = row[i];
        mn = fminf(mn, v);
        mx = fmaxf(mx, v);
    }
    #pragma unroll
    for (int o = 16; o > 0; o >>= 1) {
        mn = fminf(mn, __shfl_xor_sync(0xffffffffu, mn, o));
        mx = fmaxf(mx, __shfl_xor_sync(0xffffffffu, mx, o));
    }
    __shared__ float smn[8], smx[8];
    const int wid = threadIdx.x >> 5, lid = threadIdx.x & 31;
    if (lid == 0) { smn[wid] = mn; smx[wid] = mx; }
    __syncthreads();
    if (threadIdx.x == 0) {
        #pragma unroll
        for (int w = 1; w < 8; ++w) {
            mn = fminf(mn, smn[w]);
            mx = fmaxf(mx, smx[w]);
        }
        out[c] = mn;
        out[C + c] = mx;
    }
}

extern "C" void kernel_launch(void* const* d_in, const int* in_sizes, int n_in,
                              void* d_out, int out_size) {
    const float* in = (const float*)d_in[0];
    float* out = (float*)d_out;

    const int C = out_size / 2;       // 1024
    const int N = in_sizes[0] / C;    // 32768

    // Fast path: N divisible by 4 and N/4 divisible by 512 (guard-free loop).
    if ((N & 3) == 0 && ((N >> 2) & 511) == 0) {
        minmax_r8_kernel<<<C, 512>>>((const float4*)in, out, C, N >> 2);
    } else {
        minmax_simple_kernel<<<C, 256>>>(in, out, C, N);
    }
}

// round 11
// speedup vs baseline: 1.0755x; 1.0075x over previous
#include <cuda_runtime.h>
#include <float.h>
#include <cstdint>

// Per-channel min/max over [C, N] fp32 (C=1024, N=32768).
// TMA-engine streaming: cp.async.bulk (global->smem) 4-stage mbarrier
// pipeline, one CTA per channel. SMs only do LDS + FMNMX; the bulk engine
// owns memory-level parallelism (4 x 8KB in flight per CTA, occ ~7/SM).

#define THREADS     256
#define STAGES      4
#define STAGE_BYTES 8192
#define STAGE_F4    (STAGE_BYTES / 16)          // 512 float4 per stage
#define PER_THREAD  (STAGE_F4 / THREADS)        // 2 float4 per thread per stage

// ---- minimal PTX helpers (inline) ----
__device__ __forceinline__ uint32_t smem_u32(const void* p) {
    uint32_t a;
    asm("{ .reg .u64 t; cvta.to.shared.u64 t, %1; cvt.u32.u64 %0, t; }"
        : "=r"(a) : "l"(p));
    return a;
}
__device__ __forceinline__ void mbar_init(uint32_t a, uint32_t cnt) {
    asm volatile("mbarrier.init.shared.b64 [%0], %1;" :: "r"(a), "r"(cnt) : "memory");
}
__device__ __forceinline__ void mbar_expect_tx(uint32_t a, uint32_t bytes) {
    asm volatile("mbarrier.arrive.expect_tx.shared.b64 _, [%0], %1;"
                 :: "r"(a), "r"(bytes) : "memory");
}
__device__ __forceinline__ void mbar_arrive(uint32_t a) {
    asm volatile("mbarrier.arrive.shared.b64 _, [%0];" :: "r"(a) : "memory");
}
__device__ __forceinline__ void mbar_wait(uint32_t a, uint32_t phase) {
    asm volatile(
        "{\n\t.reg .pred P;\n\t"
        "WL_%=:\n\t"
        "mbarrier.try_wait.parity.acquire.cta.shared::cta.b64 P, [%0], %1, 0x989680;\n\t"
        "@P bra.uni WD_%=;\n\t"
        "bra.uni WL_%=;\n\t"
        "WD_%=:\n\t}"
        :: "r"(a), "r"(phase) : "memory");
}
__device__ __forceinline__ void bulk_g2s(uint32_t dst, const void* src,
                                         uint32_t bytes, uint32_t mbar) {
    asm volatile(
        "cp.async.bulk.shared::cluster.global.mbarrier::complete_tx::bytes "
        "[%0], [%1], %2, [%3];"
        :: "r"(dst), "l"(src), "r"(bytes), "r"(mbar) : "memory");
}

__global__ void __launch_bounds__(THREADS)
minmax_tma_kernel(const float* __restrict__ in, float* __restrict__ out,
                  int C, int N) {
    __shared__ __align__(128) float4   buf[STAGES][STAGE_F4];
    __shared__ __align__(8)   uint64_t bar_full[STAGES];
    __shared__ __align__(8)   uint64_t bar_empty[STAGES];
    __shared__ float smn[8], smx[8];

    const int tid = threadIdx.x;
    const int c   = blockIdx.x;

    const uint32_t full0  = smem_u32(&bar_full[0]);
    const uint32_t empty0 = smem_u32(&bar_empty[0]);
    const uint32_t buf0   = smem_u32(&buf[0][0]);

    const int nchunks = (N * 4) / STAGE_BYTES;   // 16 for N=32768
    const char* src = (const char*)(in + (size_t)c * N);

    if (tid == 0) {
        #pragma unroll
        for (int s = 0; s < STAGES; ++s) {
            mbar_init(full0  + s * 8, 1);        // completed by expect_tx + tx bytes
            mbar_init(empty0 + s * 8, THREADS);  // all consumers arrive
        }
        asm volatile("fence.proxy.async.shared::cta;" ::: "memory");
    }
    __syncthreads();

    // Prologue: fill all stages.
    if (tid == 0) {
        const int pro = nchunks < STAGES ? nchunks : STAGES;
        for (int s = 0; s < pro; ++s) {
            mbar_expect_tx(full0 + s * 8, STAGE_BYTES);
            bulk_g2s(buf0 + s * STAGE_BYTES, src + (size_t)s * STAGE_BYTES,
                     STAGE_BYTES, full0 + s * 8);
        }
    }

    float mn = FLT_MAX;
    float mx = -FLT_MAX;

    for (int k = 0; k < nchunks; ++k) {
        const int s  = k & (STAGES - 1);
        const uint32_t pf = (uint32_t)((k >> 2) & 1);   // round parity

        mbar_wait(full0 + s * 8, pf);

        #pragma unroll
        for (int u = 0; u < PER_THREAD; ++u) {
            float4 v = buf[s][tid + u * THREADS];
            mn = fminf(mn, fminf(fminf(v.x, v.y), fminf(v.z, v.w)));
            mx = fmaxf(mx, fmaxf(fmaxf(v.x, v.y), fmaxf(v.z, v.w)));
        }

        mbar_arrive(empty0 + s * 8);

        // Producer: refill this stage with chunk k+STAGES once all consumed.
        if (tid == 0 && k + STAGES < nchunks) {
            mbar_wait(empty0 + s * 8, pf);
            mbar_expect_tx(full0 + s * 8, STAGE_BYTES);
            bulk_g2s(buf0 + s * STAGE_BYTES,
                     src + (size_t)(k + STAGES) * STAGE_BYTES,
                     STAGE_BYTES, full0 + s * 8);
        }
    }

    // Warp butterfly reduction
    #pragma unroll
    for (int o = 16; o > 0; o >>= 1) {
        mn = fminf(mn, __shfl_xor_sync(0xffffffffu, mn, o));
        mx = fmaxf(mx, __shfl_xor_sync(0xffffffffu, mx, o));
    }

    const int wid = tid >> 5;
    const int lid = tid & 31;
    if (lid == 0) { smn[wid] = mn; smx[wid] = mx; }
    __syncthreads();

    if (tid == 0) {
        #pragma unroll
        for (int w = 1; w < 8; ++w) {
            mn = fminf(mn, smn[w]);
            mx = fmaxf(mx, smx[w]);
        }
        out[c]     = mn;   // min_vals
        out[C + c] = mx;   // max_vals
    }
}

// Best LDG kernel (R8): 512 threads, occ 4, guard-free float4 stream.
__global__ void __launch_bounds__(512, 4)
minmax_r8_kernel(const float4* __restrict__ in, float* __restrict__ out,
                 int C, int N4) {
    const int c = blockIdx.x;
    const float4* __restrict__ p = in + (size_t)c * N4 + threadIdx.x;
    const int iters = N4 >> 9;

    float mn = FLT_MAX, mx = -FLT_MAX;
    #pragma unroll 8
    for (int k = 0; k < iters; ++k) {
        float4 v = p[(size_t)k * 512];
        mn = fminf(mn, fminf(fminf(v.x, v.y), fminf(v.z, v.w)));
        mx = fmaxf(mx, fmaxf(fmaxf(v.x, v.y), fmaxf(v.z, v.w)));
    }
    #pragma unroll
    for (int o = 16; o > 0; o >>= 1) {
        mn = fminf(mn, __shfl_xor_sync(0xffffffffu, mn, o));
        mx = fmaxf(mx, __shfl_xor_sync(0xffffffffu, mx, o));
    }
    __shared__ float smn[16], smx[16];
    const int wid = threadIdx.x >> 5, lid = threadIdx.x & 31;
    if (lid == 0) { smn[wid] = mn; smx[wid] = mx; }
    __syncthreads();
    if (wid == 0) {
        mn = (lid < 16) ? smn[lid] : FLT_MAX;
        mx = (lid < 16) ? smx[lid] : -FLT_MAX;
        #pragma unroll
        for (int o = 8; o > 0; o >>= 1) {
            mn = fminf(mn, __shfl_xor_sync(0xffffffffu, mn, o));
            mx = fmaxf(mx, __shfl_xor_sync(0xffffffffu, mx, o));
        }
        if (lid == 0) { out[c] = mn; out[C + c] = mx; }
    }
}

// Fallback: scalar-safe for any N.
__global__ void __launch_bounds__(256)
minmax_simple_kernel(const float* __restrict__ in, float* __restrict__ out,
                     int C, int N) {
    const int c = blockIdx.x;
    const float* row = in + (size_t)c * N;
    float mn = FLT_MAX, mx = -FLT_MAX;
    for (int i = threadIdx.x; i < N; i += 256) {
        float v = row[i];
        mn = fminf(mn, v);
        mx = fmaxf(mx, v);
    }
    #pragma unroll
    for (int o = 16; o > 0; o >>= 1) {
        mn = fminf(mn, __shfl_xor_sync(0xffffffffu, mn, o));
        mx = fmaxf(mx, __shfl_xor_sync(0xffffffffu, mx, o));
    }
    __shared__ float smn[8], smx[8];
    const int wid = threadIdx.x >> 5, lid = threadIdx.x & 31;
    if (lid == 0) { smn[wid] = mn; smx[wid] = mx; }
    __syncthreads();
    if (threadIdx.x == 0) {
        #pragma unroll
        for (int w = 1; w < 8; ++w) {
            mn = fminf(mn, smn[w]);
            mx = fmaxf(mx, smx[w]);
        }
        out[c] = mn;
        out[C + c] = mx;
    }
}

extern "C" void kernel_launch(void* const* d_in, const int* in_sizes, int n_in,
                              void* d_out, int out_size) {
    const float* in = (const float*)d_in[0];
    float* out = (float*)d_out;

    const int C = out_size / 2;       // 1024
    const int N = in_sizes[0] / C;    // 32768

    if ((N % (STAGE_BYTES / 4)) == 0) {
        // TMA bulk pipeline path (N divisible by 2048).
        minmax_tma_kernel<<<C, THREADS>>>(in, out, C, N);
    } else if ((N & 3) == 0 && ((N >> 2) & 511) == 0) {
        minmax_r8_kernel<<<C, 512>>>((const float4*)in, out, C, N >> 2);
    } else {
        minmax_simple_kernel<<<C, 256>>>(in, out, C, N);
    }
}

// round 13
// speedup vs baseline: 1.0906x; 1.0140x over previous
#include <cuda_runtime.h>
#include <float.h>

// Per-channel min/max over [C, N] fp32 (C=1024, N=32768).
// Converged configuration (R8 + full unroll): one CTA per channel,
// 512 threads, occ cap 4 (64 warps/SM = 100% theoretical occupancy),
// guard-free fully-unrolled float4 stream.
//
// Measured across 7 structural variants (LDG 256t/512t, split-4+atomics,
// dual-stream, batch-8 reg arrays, cg/cs cache ops, TMA bulk pipeline):
// all land 5.3-5.8 TB/s -> the plateau is the path-independent LTS cap at
// this part's NAT clock. This kernel hits 5.82 TB/s = ~98% of that ceiling.

__global__ void __launch_bounds__(512, 4)
minmax_final_kernel(const float4* __restrict__ in, float* __restrict__ out,
                    int C, int N4) {
    const int c = blockIdx.x;
    const float4* __restrict__ p = in + (size_t)c * N4 + threadIdx.x;

    const int iters = N4 >> 9;          // N4 / 512 (16 for N=32768, exact)

    float mn = FLT_MAX;
    float mx = -FLT_MAX;

    #pragma unroll 16
    for (int k = 0; k < iters; ++k) {
        float4 v = p[(size_t)k * 512];
        mn = fminf(mn, fminf(fminf(v.x, v.y), fminf(v.z, v.w)));
        mx = fmaxf(mx, fmaxf(fmaxf(v.x, v.y), fmaxf(v.z, v.w)));
    }

    // Warp butterfly reduction
    #pragma unroll
    for (int o = 16; o > 0; o >>= 1) {
        mn = fminf(mn, __shfl_xor_sync(0xffffffffu, mn, o));
        mx = fmaxf(mx, __shfl_xor_sync(0xffffffffu, mx, o));
    }

    __shared__ float smn[16], smx[16];
    const int wid = threadIdx.x >> 5;
    const int lid = threadIdx.x & 31;
    if (lid == 0) { smn[wid] = mn; smx[wid] = mx; }
    __syncthreads();

    // Final reduce across 16 warp partials by warp 0.
    if (wid == 0) {
        mn = (lid < 16) ? smn[lid] : FLT_MAX;
        mx = (lid < 16) ? smx[lid] : -FLT_MAX;
        #pragma unroll
        for (int o = 8; o > 0; o >>= 1) {
            mn = fminf(mn, __shfl_xor_sync(0xffffffffu, mn, o));
            mx = fmaxf(mx, __shfl_xor_sync(0xffffffffu, mx, o));
        }
        if (lid == 0) {
            out[c]     = mn;   // min_vals
            out[C + c] = mx;   // max_vals
        }
    }
}

// Fallback: one CTA per channel, scalar-safe (any N).
__global__ void __launch_bounds__(256)
minmax_simple_kernel(const float* __restrict__ in, float* __restrict__ out,
                     int C, int N) {
    const int c = blockIdx.x;
    const float* row = in + (size_t)c * N;
    float mn = FLT_MAX, mx = -FLT_MAX;
    for (int i = threadIdx.x; i < N; i += 256) {
        float v = row[i];
        mn = fminf(mn, v);
        mx = fmaxf(mx, v);
    }
    #pragma unroll
    for (int o = 16; o > 0; o >>= 1) {
        mn = fminf(mn, __shfl_xor_sync(0xffffffffu, mn, o));
        mx = fmaxf(mx, __shfl_xor_sync(0xffffffffu, mx, o));
    }
    __shared__ float smn[8], smx[8];
    const int wid = threadIdx.x >> 5, lid = threadIdx.x & 31;
    if (lid == 0) { smn[wid] = mn; smx[wid] = mx; }
    __syncthreads();
    if (threadIdx.x == 0) {
        #pragma unroll
        for (int w = 1; w < 8; ++w) {
            mn = fminf(mn, smn[w]);
            mx = fmaxf(mx, smx[w]);
        }
        out[c] = mn;
        out[C + c] = mx;
    }
}

extern "C" void kernel_launch(void* const* d_in, const int* in_sizes, int n_in,
                              void* d_out, int out_size) {
    const float* in = (const float*)d_in[0];
    float* out = (float*)d_out;

    const int C = out_size / 2;       // 1024
    const int N = in_sizes[0] / C;    // 32768

    // Fast path: N divisible by 4 and N/4 divisible by 512 (guard-free loop).
    if ((N & 3) == 0 && ((N >> 2) & 511) == 0) {
        minmax_final_kernel<<<C, 512>>>((const float4*)in, out, C, N >> 2);
    } else {
        minmax_simple_kernel<<<C, 256>>>(in, out, C, N);
    }
}